// round 7
// baseline (speedup 1.0000x reference)
#include <cuda_runtime.h>
#include <math.h>

#define VOCAB 30000
#define HID   512
#define NCLS  4
#define NEDGE 4096
#define NNODE (NEDGE + 1)
#define KW    32
#define G3    (3 * HID)      // 1536
#define NLEV_MAX 40          // tree depth ~22; 40 verified sufficient in rounds 3/5

// -------------------- static device scratch (no allocations allowed) --------
__device__ float d_Et[(size_t)VOCAB * HID];
__device__ float d_X [(size_t)NEDGE * HID];
__device__ float d_GI[(size_t)NEDGE * G3];
__device__ float d_GH[(size_t)NEDGE * G3];
__device__ float d_H [(size_t)NNODE * HID];
__device__ int   d_order[NEDGE];
__device__ int   d_levelStart[NLEV_MAX + 2];
__device__ unsigned char d_leaf[NNODE];
__device__ unsigned d_finU[HID];

// -------------------- tf32 helpers (3xTF32 error-compensated MMA) -----------
__device__ __forceinline__ unsigned f2tf(float v) {
    unsigned r; asm("cvt.rna.tf32.f32 %0, %1;" : "=r"(r) : "f"(v)); return r;
}
__device__ __forceinline__ void split_tf(float v, float& hi, float& lo) {
    hi = __uint_as_float(f2tf(v));
    lo = __uint_as_float(f2tf(v - hi));
}
__device__ __forceinline__ void mma8(float c[4], const unsigned a[4], const unsigned b[2]) {
    asm volatile("mma.sync.aligned.m16n8k8.row.col.f32.tf32.tf32.f32 "
                 "{%0,%1,%2,%3},{%4,%5,%6,%7},{%8,%9},{%0,%1,%2,%3};"
                 : "+f"(c[0]), "+f"(c[1]), "+f"(c[2]), "+f"(c[3])
                 : "r"(a[0]), "r"(a[1]), "r"(a[2]), "r"(a[3]), "r"(b[0]), "r"(b[1]));
}

#define TKC  16
#define TPAD 20   // row*20 mod 32 over 8 rows -> 8 distinct banks (conflict-free)

// -------------------- 1) transpose E (HID,VOCAB) -> (VOCAB,HID) -------------
__global__ void k_transpose(const float* __restrict__ E) {
    __shared__ float t[32][33];
    int v0 = blockIdx.x * 32, h0 = blockIdx.y * 32;
    int vx = v0 + threadIdx.x;
#pragma unroll
    for (int i = 0; i < 32; i += 8) {
        int h = h0 + threadIdx.y + i;
        if (vx < VOCAB) t[threadIdx.y + i][threadIdx.x] = E[(size_t)h * VOCAB + vx];
    }
    __syncthreads();
    int hx = h0 + threadIdx.x;
#pragma unroll
    for (int i = 0; i < 32; i += 8) {
        int v = v0 + threadIdx.y + i;
        if (v < VOCAB) d_Et[(size_t)v * HID + hx] = t[threadIdx.x][threadIdx.y + i];
    }
}

// -------------------- 2) x[c] = sum_k Et[idx[c][k]] * w[c][k] ---------------
__global__ void k_embed(const float* __restrict__ word, const int* __restrict__ widx) {
    int c = blockIdx.x;
    __shared__ int   si[KW];
    __shared__ float sw[KW];
    if (threadIdx.x < KW) {
        si[threadIdx.x] = widx[c * KW + threadIdx.x];
        sw[threadIdx.x] = word[c * KW + threadIdx.x];
    }
    __syncthreads();
    int h = threadIdx.x;
    float a0 = 0.f, a1 = 0.f, a2 = 0.f, a3 = 0.f;
#pragma unroll 4
    for (int k = 0; k < KW; k++) {
        const float* ep = &d_Et[(size_t)si[k] * HID];
        float wk = sw[k];
        a0 += ep[h]       * wk;
        a1 += ep[h + 128] * wk;
        a2 += ep[h + 256] * wk;
        a3 += ep[h + 384] * wk;
    }
    float* xp = &d_X[(size_t)c * HID];
    xp[h] = a0; xp[h + 128] = a1; xp[h + 256] = a2; xp[h + 384] = a3;
}

// -------------------- 3) GI = X @ W_ih^T + b_ih via 3xTF32 MMA --------------
// Block tile 128(nodes) x 64(gate rows), K chunk 16. 8 warps = 4x2, warp tile 32x32.
__global__ __launch_bounds__(256) void k_gi(const float* __restrict__ Wih,
                                            const float* __restrict__ bih) {
    __shared__ float Ah[128][TPAD], Al[128][TPAD];   // 10240 B each
    __shared__ float Bh[64][TPAD],  Bl[64][TPAD];    // 5120 B each  => 30720 total
    int m0 = blockIdx.y * 128, n0 = blockIdx.x * 64;
    int tid = threadIdx.x, warp = tid >> 5, lane = tid & 31;
    int wm = (warp >> 1) * 32, wn = (warp & 1) * 32;
    int g = lane >> 2, q = lane & 3;
    int lr4 = tid >> 2;            // 0..63
    int lk4 = (tid & 3) * 4;       // 0,4,8,12

    float c[2][4][4];
#pragma unroll
    for (int mi = 0; mi < 2; mi++)
#pragma unroll
        for (int ni = 0; ni < 4; ni++)
#pragma unroll
            for (int x = 0; x < 4; x++) c[mi][ni][x] = 0.f;

    for (int k0 = 0; k0 < HID; k0 += TKC) {
#pragma unroll
        for (int p = 0; p < 2; p++) {            // X tile: 128 x 16
            int r = lr4 + p * 64;
            float4 v = *(const float4*)&d_X[(size_t)(m0 + r) * HID + k0 + lk4];
            split_tf(v.x, Ah[r][lk4 + 0], Al[r][lk4 + 0]);
            split_tf(v.y, Ah[r][lk4 + 1], Al[r][lk4 + 1]);
            split_tf(v.z, Ah[r][lk4 + 2], Al[r][lk4 + 2]);
            split_tf(v.w, Ah[r][lk4 + 3], Al[r][lk4 + 3]);
        }
        {                                        // Wih tile: 64 x 16
            int r = lr4;
            float4 v = *(const float4*)&Wih[(size_t)(n0 + r) * HID + k0 + lk4];
            split_tf(v.x, Bh[r][lk4 + 0], Bl[r][lk4 + 0]);
            split_tf(v.y, Bh[r][lk4 + 1], Bl[r][lk4 + 1]);
            split_tf(v.z, Bh[r][lk4 + 2], Bl[r][lk4 + 2]);
            split_tf(v.w, Bh[r][lk4 + 3], Bl[r][lk4 + 3]);
        }
        __syncthreads();
#pragma unroll
        for (int k8 = 0; k8 < TKC; k8 += 8) {
            unsigned ah[2][4], al[2][4];
#pragma unroll
            for (int mi = 0; mi < 2; mi++) {
                int rb = wm + mi * 16;
                ah[mi][0] = __float_as_uint(Ah[rb + g][k8 + q]);
                ah[mi][1] = __float_as_uint(Ah[rb + 8 + g][k8 + q]);
                ah[mi][2] = __float_as_uint(Ah[rb + g][k8 + q + 4]);
                ah[mi][3] = __float_as_uint(Ah[rb + 8 + g][k8 + q + 4]);
                al[mi][0] = __float_as_uint(Al[rb + g][k8 + q]);
                al[mi][1] = __float_as_uint(Al[rb + 8 + g][k8 + q]);
                al[mi][2] = __float_as_uint(Al[rb + g][k8 + q + 4]);
                al[mi][3] = __float_as_uint(Al[rb + 8 + g][k8 + q + 4]);
            }
#pragma unroll
            for (int ni = 0; ni < 4; ni++) {
                int nb = wn + ni * 8;
                unsigned bh[2] = {__float_as_uint(Bh[nb + g][k8 + q]),
                                  __float_as_uint(Bh[nb + g][k8 + q + 4])};
                unsigned bl[2] = {__float_as_uint(Bl[nb + g][k8 + q]),
                                  __float_as_uint(Bl[nb + g][k8 + q + 4])};
#pragma unroll
                for (int mi = 0; mi < 2; mi++) {
                    mma8(c[mi][ni], ah[mi], bh);
                    mma8(c[mi][ni], ah[mi], bl);
                    mma8(c[mi][ni], al[mi], bh);
                }
            }
        }
        __syncthreads();
    }
#pragma unroll
    for (int mi = 0; mi < 2; mi++) {
        int row = m0 + wm + mi * 16 + g;
#pragma unroll
        for (int ni = 0; ni < 4; ni++) {
            int col = n0 + wn + ni * 8 + 2 * q;
            float b0 = bih[col], b1 = bih[col + 1];
            *(float2*)&d_GI[(size_t)row * G3 + col] =
                make_float2(c[mi][ni][0] + b0, c[mi][ni][1] + b1);
            *(float2*)&d_GI[(size_t)(row + 8) * G3 + col] =
                make_float2(c[mi][ni][2] + b0, c[mi][ni][3] + b1);
        }
    }
}

// -------------------- 4) levels via pointer jumping + counting sort ---------
__global__ void k_levels(const int* __restrict__ tree) {
    __shared__ int anc[NNODE];
    __shared__ int dep[NNODE];
    __shared__ int s_max;
    int t = threadIdx.x, NT = blockDim.x;     // 512

    for (int c = t; c < NNODE; c += NT) {
        if (c == 0) { anc[0] = 0; dep[0] = 0; }
        else        { anc[c] = tree[2 * (c - 1)]; dep[c] = 1; }
        d_leaf[c] = 1;
    }
    if (t == 0) s_max = 0;
    for (int u = t; u < HID; u += NT) { d_finU[u] = 0u; d_H[u] = 0.f; }
    __syncthreads();

    for (int it = 0; it < 13; it++) {
        int na[9], nd[9];
        int i = 0;
        for (int c = t; c < NNODE; c += NT, i++) {
            int a = anc[c];
            nd[i] = dep[c] + dep[a];
            na[i] = anc[a];
        }
        __syncthreads();
        i = 0;
        for (int c = t; c < NNODE; c += NT, i++) { dep[c] = nd[i]; anc[c] = na[i]; }
        __syncthreads();
    }

    int lm = 0;
    for (int c = t; c < NNODE; c += NT) lm = max(lm, dep[c]);
    atomicMax(&s_max, lm);
    for (int e = t; e < NEDGE; e += NT) d_leaf[tree[2 * e]] = 0;
    for (int c = t; c < NNODE; c += NT) anc[c] = 0;
    __syncthreads();
    for (int c = t; c < NNODE; c += NT)
        if (c > 0) atomicAdd(&anc[dep[c]], 1);
    __syncthreads();
    if (t == 0) {
        int ml = s_max;
        int run = 0;
        for (int l = 1; l <= NLEV_MAX; l++) {
            d_levelStart[l] = run;
            if (l <= ml) {
                int h = anc[l];
                anc[l] = run;
                run += h;
            }
        }
        d_levelStart[0] = 0;
        d_levelStart[NLEV_MAX + 1] = run;      // == NEDGE
    }
    __syncthreads();
    for (int c = t; c < NNODE; c += NT)
        if (c > 0) {
            int pos = atomicAdd(&anc[dep[c]], 1);
            d_order[pos] = c;
        }
}

// -------------------- 5a) per-level GH GEMM via 3xTF32 MMA ------------------
// GH[c][r] = sum_k Whh[r][k] * H[parent(c)][k], tile 64(rows) x 32(nodes).
// 8 warps = 2(m) x 4(n); warp tile 32 rows x 8 nodes.
#define GHM 64
#define GHN 32
#define GH_ROWB (G3 / GHM)   // 24
__global__ __launch_bounds__(256) void k_gh(int lev, const int* __restrict__ tree,
                                            const float* __restrict__ Whh,
                                            const float* __restrict__ bhh) {
    int s = d_levelStart[lev], e = d_levelStart[lev + 1];
    int cnt = e - s;
    if (cnt <= 0) return;
    __shared__ float Ah[GHM][TPAD], Al[GHM][TPAD];   // 5120 B each
    __shared__ float Bh[GHN][TPAD], Bl[GHN][TPAD];   // 2560 B each => 15360 total
    __shared__ int sp[GHN], sc[GHN];
    int tid = threadIdx.x, warp = tid >> 5, lane = tid & 31;
    int wm = (warp >> 2) * 32;    // 0 or 32
    int wn = (warp & 3) * 8;      // 0,8,16,24
    int g = lane >> 2, q = lane & 3;
    int lr4 = tid >> 2;           // 0..63
    int lk4 = (tid & 3) * 4;      // 0,4,8,12
    int nodeBlocks = (cnt + GHN - 1) / GHN;
    int tiles = nodeBlocks * GH_ROWB;

    for (int t = blockIdx.x; t < tiles; t += gridDim.x) {
        int rb = t % GH_ROWB, nb = t / GH_ROWB;
        int r0 = rb * GHM, j0 = nb * GHN;
        if (tid < GHN) {
            int jj = j0 + tid; if (jj >= cnt) jj = cnt - 1;
            int cl = d_order[s + jj];
            sp[tid] = tree[2 * (cl - 1)];
            sc[tid] = cl - 1;
        }
        __syncthreads();

        float c[2][4];
#pragma unroll
        for (int mi = 0; mi < 2; mi++)
#pragma unroll
            for (int x = 0; x < 4; x++) c[mi][x] = 0.f;

        for (int k0 = 0; k0 < HID; k0 += TKC) {
            {                                    // Whh tile: 64 x 16
                int r = lr4;
                float4 v = *(const float4*)&Whh[(size_t)(r0 + r) * HID + k0 + lk4];
                split_tf(v.x, Ah[r][lk4 + 0], Al[r][lk4 + 0]);
                split_tf(v.y, Ah[r][lk4 + 1], Al[r][lk4 + 1]);
                split_tf(v.z, Ah[r][lk4 + 2], Al[r][lk4 + 2]);
                split_tf(v.w, Ah[r][lk4 + 3], Al[r][lk4 + 3]);
            }
            if (tid < 128) {                     // H gathered tile: 32 x 16
                int j = tid >> 2;
                float4 v = *(const float4*)&d_H[(size_t)sp[j] * HID + k0 + lk4];
                split_tf(v.x, Bh[j][lk4 + 0], Bl[j][lk4 + 0]);
                split_tf(v.y, Bh[j][lk4 + 1], Bl[j][lk4 + 1]);
                split_tf(v.z, Bh[j][lk4 + 2], Bl[j][lk4 + 2]);
                split_tf(v.w, Bh[j][lk4 + 3], Bl[j][lk4 + 3]);
            }
            __syncthreads();
#pragma unroll
            for (int k8 = 0; k8 < TKC; k8 += 8) {
                unsigned ah[2][4], al[2][4];
#pragma unroll
                for (int mi = 0; mi < 2; mi++) {
                    int rbb = wm + mi * 16;
                    ah[mi][0] = __float_as_uint(Ah[rbb + g][k8 + q]);
                    ah[mi][1] = __float_as_uint(Ah[rbb + 8 + g][k8 + q]);
                    ah[mi][2] = __float_as_uint(Ah[rbb + g][k8 + q + 4]);
                    ah[mi][3] = __float_as_uint(Ah[rbb + 8 + g][k8 + q + 4]);
                    al[mi][0] = __float_as_uint(Al[rbb + g][k8 + q]);
                    al[mi][1] = __float_as_uint(Al[rbb + 8 + g][k8 + q]);
                    al[mi][2] = __float_as_uint(Al[rbb + g][k8 + q + 4]);
                    al[mi][3] = __float_as_uint(Al[rbb + 8 + g][k8 + q + 4]);
                }
                unsigned bh[2] = {__float_as_uint(Bh[wn + g][k8 + q]),
                                  __float_as_uint(Bh[wn + g][k8 + q + 4])};
                unsigned bl[2] = {__float_as_uint(Bl[wn + g][k8 + q]),
                                  __float_as_uint(Bl[wn + g][k8 + q + 4])};
#pragma unroll
                for (int mi = 0; mi < 2; mi++) {
                    mma8(c[mi], ah[mi], bh);
                    mma8(c[mi], ah[mi], bl);
                    mma8(c[mi], al[mi], bh);
                }
            }
            __syncthreads();
        }
        // store: c[mi] = {(row,col),(row,col+1),(row+8,col),(row+8,col+1)}
#pragma unroll
        for (int mi = 0; mi < 2; mi++) {
            int row = r0 + wm + mi * 16 + g;
            int colL = wn + 2 * q;
            float br0 = bhh[row], br8 = bhh[row + 8];
            if (j0 + colL < cnt) {
                size_t b = (size_t)sc[colL] * G3;
                d_GH[b + row]     = c[mi][0] + br0;
                d_GH[b + row + 8] = c[mi][2] + br8;
            }
            if (j0 + colL + 1 < cnt) {
                size_t b = (size_t)sc[colL + 1] * G3;
                d_GH[b + row]     = c[mi][1] + br0;
                d_GH[b + row + 8] = c[mi][3] + br8;
            }
        }
        __syncthreads();
    }
}

// -------------------- 5b) per-level GRU combine -----------------------------
__global__ __launch_bounds__(256) void k_combine(int lev, const int* __restrict__ tree) {
    int s = d_levelStart[lev], e = d_levelStart[lev + 1];
    int total = (e - s) * HID;
    for (int idx = blockIdx.x * blockDim.x + threadIdx.x; idx < total;
         idx += gridDim.x * blockDim.x) {
        int j = s + (idx >> 9);
        int u = idx & 511;
        int c = d_order[j];
        size_t gb = (size_t)(c - 1) * G3;
        float gr = d_GI[gb + u], gz = d_GI[gb + HID + u], gn = d_GI[gb + 2 * HID + u];
        float hr = d_GH[gb + u], hz = d_GH[gb + HID + u], hn = d_GH[gb + 2 * HID + u];
        float r = 1.f / (1.f + __expf(-(gr + hr)));
        float z = 1.f / (1.f + __expf(-(gz + hz)));
        float n = tanhf(gn + r * hn);
        int p = tree[2 * (c - 1)];
        float hpu = d_H[(size_t)p * HID + u];
        d_H[(size_t)c * HID + u] = (1.f - z) * n + z * hpu;
    }
}

// -------------------- 6a) parallel leaf max (order-preserving uint) ---------
__global__ __launch_bounds__(512) void k_final1() {
    int u = threadIdx.x;
    int c0 = blockIdx.x * 64;
    float m = -2.f;                   // |h| <= 1 by GRU construction
#pragma unroll 4
    for (int i = 0; i < 64; i++) {
        int c = c0 + i;
        if (c < NNODE && d_leaf[c]) m = fmaxf(m, d_H[(size_t)c * HID + u]);
    }
    unsigned bits = __float_as_uint(m);
    unsigned enc = (bits & 0x80000000u) ? ~bits : (bits | 0x80000000u);
    atomicMax(&d_finU[u], enc);
}

// -------------------- 6b) logits + softmax ----------------------------------
__global__ void k_final2(const float* __restrict__ outW, const float* __restrict__ outb,
                         float* __restrict__ out) {
    __shared__ float fin[HID];
    __shared__ float logits[NCLS];
    int t = threadIdx.x;              // 128 threads
    for (int u = t; u < HID; u += 128) {
        unsigned enc = d_finU[u];
        unsigned bits = (enc & 0x80000000u) ? (enc & 0x7FFFFFFFu) : ~enc;
        fin[u] = __uint_as_float(bits);
    }
    __syncthreads();
    int cls = t >> 5, lane = t & 31;
    float s = 0.f;
    for (int u = lane; u < HID; u += 32) s += outW[cls * HID + u] * fin[u];
#pragma unroll
    for (int o = 16; o > 0; o >>= 1) s += __shfl_down_sync(0xffffffffu, s, o);
    if (lane == 0) logits[cls] = s + outb[cls];
    __syncthreads();
    if (t == 0) {
        float mx = logits[0];
        for (int i = 1; i < NCLS; i++) mx = fmaxf(mx, logits[i]);
        float ex[NCLS], sm = 0.f;
        for (int i = 0; i < NCLS; i++) { ex[i] = expf(logits[i] - mx); sm += ex[i]; }
        for (int i = 0; i < NCLS; i++) out[i] = ex[i] / sm;
    }
}

// -------------------- launcher ----------------------------------------------
extern "C" void kernel_launch(void* const* d_in, const int* in_sizes, int n_in,
                              void* d_out, int out_size) {
    const int*   tree = (const int*)  d_in[0];
    const float* word = (const float*)d_in[1];
    const int*   widx = (const int*)  d_in[2];
    const float* Etab = (const float*)d_in[3];
    const float* Wih  = (const float*)d_in[4];
    const float* Whh  = (const float*)d_in[5];
    const float* bih  = (const float*)d_in[6];
    const float* bhh  = (const float*)d_in[7];
    const float* outW = (const float*)d_in[8];
    const float* outb = (const float*)d_in[9];
    float* out = (float*)d_out;

    k_transpose<<<dim3((VOCAB + 31) / 32, HID / 32), dim3(32, 8)>>>(Etab);
    k_embed<<<NEDGE, 128>>>(word, widx);
    k_gi<<<dim3(G3 / 64, NEDGE / 128), 256>>>(Wih, bih);
    k_levels<<<1, 512>>>(tree);
    for (int lev = 1; lev <= NLEV_MAX; lev++) {
        k_gh<<<192, 256>>>(lev, tree, Whh, bhh);
        k_combine<<<128, 256>>>(lev, tree);
    }
    k_final1<<<(NNODE + 63) / 64, 512>>>();
    k_final2<<<1, 128>>>(outW, outb, out);
}